// round 9
// baseline (speedup 1.0000x reference)
#include <cuda_runtime.h>
#include <cstdint>
#include <cstddef>

// ============================================================================
// AlignToZWignerD: D^l (l=0..4) Wigner blocks for real spherical harmonics,
// Ivanic-Ruedenberg recurrence, fully unrolled at compile time.
// Output (N, 25, 25) fp32, block-diagonal. N = 200000.
//
// Per-CTA (32 points, 1 warp):
//   1) zero-fill 80 KB smem mirror of the CTA's output region (STS.128)
//   2) compute D-blocks in registers; owner thread scatters 165 nonzeros to
//      its smem row at compile-time offsets (conflict-free STS.32)
//   3) flat copy smem -> gmem as LDS.128 + STG.128 (no ALU beyond induction)
// ============================================================================

#define PTS 32
#define ROWF 625                    // floats per point (25*25)
#define SMEM_FLOATS (PTS * ROWF)    // 20000 floats = 80000 B
#define SMEM_BYTES (SMEM_FLOATS * 4)

// ---------------- compile-time sqrt (Newton, double) ----------------
constexpr __host__ __device__ double csqrt_(double x) {
    if (x <= 0.0) return 0.0;
    double r = x > 1.0 ? x : 1.0;
    for (int i = 0; i < 60; i++) r = 0.5 * (r + x / r);
    return r;
}

// ---------------- compile-time u, v, w coefficients ----------------
constexpr __host__ __device__ double denom_(int l, int mp) {
    return (mp == l || mp == -l) ? double((2 * l) * (2 * l - 1))
                                 : double((l + mp) * (l - mp));
}
constexpr __host__ __device__ double u_of(int l, int m, int mp) {
    return csqrt_(double((l + m) * (l - m)) / denom_(l, mp));
}
constexpr __host__ __device__ double v_of(int l, int m, int mp) {
    int am = m < 0 ? -m : m;
    double d0 = (m == 0) ? 1.0 : 0.0;
    return 0.5 * csqrt_((1.0 + d0) * double((l + am - 1) * (l + am)) / denom_(l, mp))
           * (1.0 - 2.0 * d0);
}
constexpr __host__ __device__ double w_of(int l, int m, int mp) {
    int am = m < 0 ? -m : m;
    double d0 = (m == 0) ? 1.0 : 0.0;
    int wn = l - am - 1; if (wn < 0) wn = 0;
    return -0.5 * csqrt_(double(wn * (l - am)) / denom_(l, mp)) * (1.0 - d0);
}

// ---------------- integer sequence (self-contained) ----------------
template <int... Is> struct ISeq {};
template <int N, int... Is> struct MkSeq : MkSeq<N - 1, N - 1, Is...> {};
template <int... Is> struct MkSeq<0, Is...> { using type = ISeq<Is...>; };

// ---------------- P term (all indices compile-time) ----------------
template <int L, int I, int A, int B>
__device__ __forceinline__ float Pt(const float (&r1)[9],
                                    const float (&dp)[(2 * L - 1) * (2 * L - 1)]) {
    constexpr int lp = L - 1, np = 2 * L - 1, row = (I + 1) * 3;
    if constexpr (B == L)
        return r1[row + 2] * dp[(A + lp) * np + 2 * lp]
             - r1[row + 0] * dp[(A + lp) * np + 0];
    else if constexpr (B == -L)
        return r1[row + 2] * dp[(A + lp) * np + 0]
             + r1[row + 0] * dp[(A + lp) * np + 2 * lp];
    else
        return r1[row + 1] * dp[(A + lp) * np + (B + lp)];
}

// ---------------- one D^L entry (coefficients are immediates) ----------------
template <int L, int M, int MP>
__device__ __forceinline__ float entry(const float (&r1)[9],
                                       const float (&dp)[(2 * L - 1) * (2 * L - 1)]) {
    constexpr float u = (float)u_of(L, M, MP);
    constexpr float v = (float)v_of(L, M, MP);
    constexpr float w = (float)w_of(L, M, MP);
    constexpr float SQ2 = 1.41421356237309515f;
    float acc = 0.0f;
    if constexpr (u != 0.0f)
        acc += u * Pt<L, 0, M, MP>(r1, dp);
    if constexpr (v != 0.0f) {
        if constexpr (M == 0) {
            acc += v * (Pt<L, 1, 1, MP>(r1, dp) + Pt<L, -1, -1, MP>(r1, dp));
        } else if constexpr (M > 0) {
            constexpr float s = (M == 1) ? SQ2 : 1.0f;
            acc += (v * s) * Pt<L, 1, M - 1, MP>(r1, dp);
            if constexpr (M != 1)
                acc -= v * Pt<L, -1, -M + 1, MP>(r1, dp);
        } else {
            if constexpr (M != -1)
                acc += v * Pt<L, 1, M + 1, MP>(r1, dp);
            constexpr float s = (M == -1) ? SQ2 : 1.0f;
            acc += (v * s) * Pt<L, -1, -M - 1, MP>(r1, dp);
        }
    }
    if constexpr (w != 0.0f) {
        if constexpr (M > 0)
            acc += w * (Pt<L, 1, M + 1, MP>(r1, dp) + Pt<L, -1, -M - 1, MP>(r1, dp));
        else
            acc += w * (Pt<L, 1, M - 1, MP>(r1, dp) - Pt<L, -1, -M + 1, MP>(r1, dp));
    }
    return acc;
}

// ---------------- build D^L into registers ----------------
template <int L, int... Is>
__device__ __forceinline__ void build_reg_impl(const float (&r1)[9],
                                               const float (&dp)[(2 * L - 1) * (2 * L - 1)],
                                               float (&dl)[(2 * L + 1) * (2 * L + 1)],
                                               ISeq<Is...>) {
    ((dl[Is] = entry<L, Is / (2 * L + 1) - L, Is % (2 * L + 1) - L>(r1, dp)), ...);
}
template <int L>
__device__ __forceinline__ void build_reg(const float (&r1)[9],
                                          const float (&dp)[(2 * L - 1) * (2 * L - 1)],
                                          float (&dl)[(2 * L + 1) * (2 * L + 1)]) {
    build_reg_impl<L>(r1, dp, dl, typename MkSeq<(2 * L + 1) * (2 * L + 1)>::type{});
}

// ---------------- output position of block-l element (i,j): compile-time ----
constexpr __host__ __device__ int opos_(int l, int i, int j) {
    return (l * l + i) * 25 + (l * l + j);
}

// ---- scatter a register block D^L into the expanded 625-float smem row ----
template <int L, int... Is>
__device__ __forceinline__ void scatter_impl(const float (&dl)[(2 * L + 1) * (2 * L + 1)],
                                             float* __restrict__ srow, ISeq<Is...>) {
    ((srow[opos_(L, Is / (2 * L + 1), Is % (2 * L + 1))] = dl[Is]), ...);
}
template <int L>
__device__ __forceinline__ void scatter_blk(const float (&dl)[(2 * L + 1) * (2 * L + 1)],
                                            float* __restrict__ srow) {
    scatter_impl<L>(dl, srow, typename MkSeq<(2 * L + 1) * (2 * L + 1)>::type{});
}

// ---- build D^4 entries and scatter directly (low register pressure) ----
template <int L, int... Is>
__device__ __forceinline__ void build_scatter_impl(const float (&r1)[9],
                                                   const float (&dp)[(2 * L - 1) * (2 * L - 1)],
                                                   float* __restrict__ srow, ISeq<Is...>) {
    ((srow[opos_(L, Is / (2 * L + 1), Is % (2 * L + 1))] =
          entry<L, Is / (2 * L + 1) - L, Is % (2 * L + 1) - L>(r1, dp)), ...);
}
template <int L>
__device__ __forceinline__ void build_scatter(const float (&r1)[9],
                                              const float (&dp)[(2 * L - 1) * (2 * L - 1)],
                                              float* __restrict__ srow) {
    build_scatter_impl<L>(r1, dp, srow, typename MkSeq<(2 * L + 1) * (2 * L + 1)>::type{});
}

// ---------------- main kernel: one warp per CTA, 32 points ----------------
__global__ void __launch_bounds__(32, 2)
AlignToZWignerD_kernel(const float* __restrict__ xyz, float* __restrict__ out, int N) {
    extern __shared__ float sm[];          // SMEM_FLOATS, flat mirror of output
    const int lane = threadIdx.x;
    const size_t blk0 = (size_t)blockIdx.x * PTS;
    const int p = (int)blk0 + lane;

    // --- phase 1: cooperative zero-fill (conflict-free STS.128) ---
    {
        float4* s4 = reinterpret_cast<float4*>(sm);
        const float4 z4 = make_float4(0.0f, 0.0f, 0.0f, 0.0f);
        #pragma unroll 8
        for (int i = lane; i < SMEM_FLOATS / 4; i += 32) s4[i] = z4;
    }

    // --- phase 2: compute + scatter nonzeros at compile-time offsets ---
    // (zero-fill and scatter touch overlapping bytes -> sync in between)
    __syncwarp();

    if (p < N) {
        float x = xyz[3 * p + 0], y = xyz[3 * p + 1], z = xyz[3 * p + 2];
        float nrm = sqrtf(x * x + y * y + z * z);
        float inv = 1.0f / fmaxf(nrm, 1e-14f);
        float vx = x * inv, vy = y * inv, vz = z * inv;
        float ct = fminf(1.0f, fmaxf(-1.0f, vz));
        float st = sqrtf(fmaxf(0.0f, 1.0f - ct * ct));
        float rxy = sqrtf(vx * vx + vy * vy);
        float cp, sp;
        if (rxy > 0.0f) { float ir = 1.0f / rxy; cp = vx * ir; sp = vy * ir; }
        else            { cp = 1.0f; sp = 0.0f; }

        // D^1 in real-SH basis (rows/cols permuted by p=[1,2,0])
        float r1[9] = { cp,      0.0f, -sp,
                        st * sp, ct,    st * cp,
                        ct * sp, -st,   ct * cp };

        float* srow = sm + lane * ROWF;    // row stride 625: bank stride 17 -> CF

        srow[opos_(0, 0, 0)] = 1.0f;
        #pragma unroll
        for (int i = 0; i < 3; i++)
            #pragma unroll
            for (int j = 0; j < 3; j++)
                srow[opos_(1, i, j)] = r1[i * 3 + j];

        float d2[25];
        build_reg<2>(r1, r1, d2);
        scatter_blk<2>(d2, srow);

        float d3[49];
        build_reg<3>(r1, d2, d3);
        scatter_blk<3>(d3, srow);

        build_scatter<4>(r1, d3, srow);    // 81 entries straight to smem
    }
    __syncwarp();

    // --- phase 3: flat copy smem -> gmem (LDS.128 + STG.128, zero ALU) ---
    if (blk0 + PTS <= (size_t)N) {
        const float4* s4 = reinterpret_cast<const float4*>(sm);
        float4* o4 = reinterpret_cast<float4*>(out + blk0 * ROWF);
        #pragma unroll 4
        for (int i = lane; i < SMEM_FLOATS / 4; i += 32) o4[i] = s4[i];
    } else {
        // tail CTA: scalar, alignment-safe
        int nf = (N - (int)blk0) * ROWF;
        float* o = out + blk0 * ROWF;
        for (int i = lane; i < nf; i += 32) o[i] = sm[i];
    }
}

// ---------------- launch ----------------
extern "C" void kernel_launch(void* const* d_in, const int* in_sizes, int n_in,
                              void* d_out, int out_size) {
    const float* xyz = (const float*)d_in[0];
    float* out = (float*)d_out;
    int N = in_sizes[0] / 3;
    int grid = (N + PTS - 1) / PTS;
    cudaFuncSetAttribute(AlignToZWignerD_kernel,
                         cudaFuncAttributeMaxDynamicSharedMemorySize, SMEM_BYTES);
    AlignToZWignerD_kernel<<<grid, 32, SMEM_BYTES>>>(xyz, out, N);
}

// round 10
// speedup vs baseline: 2.0859x; 2.0859x over previous
#include <cuda_runtime.h>
#include <cstdint>
#include <cstddef>

// ============================================================================
// AlignToZWignerD: D^l (l=0..4) Wigner blocks for real spherical harmonics,
// Ivanic-Ruedenberg recurrence, fully unrolled at compile time.
// Output (N, 25, 25) fp32, block-diagonal. N = 200000.
// Skeleton: 1 warp / CTA, 32 points, compact 21 KB smem, 10 CTAs/SM.
// Writeback: coalesced STG.32 stream, zero elements stored from registers
// (no LDS), nonzeros gathered from smem; streaming (.cs) stores.
// ============================================================================

#define COMPACT 165       // 1 + 9 + 25 + 49 + 81
#define ROWSTRIDE 167     // pad: gcd(167,32)=1 -> conflict-free smem access

// ---------------- compile-time sqrt (Newton, double) ----------------
constexpr __host__ __device__ double csqrt_(double x) {
    if (x <= 0.0) return 0.0;
    double r = x > 1.0 ? x : 1.0;
    for (int i = 0; i < 60; i++) r = 0.5 * (r + x / r);
    return r;
}

// ---------------- compile-time u, v, w coefficients ----------------
constexpr __host__ __device__ double denom_(int l, int mp) {
    return (mp == l || mp == -l) ? double((2 * l) * (2 * l - 1))
                                 : double((l + mp) * (l - mp));
}
constexpr __host__ __device__ double u_of(int l, int m, int mp) {
    return csqrt_(double((l + m) * (l - m)) / denom_(l, mp));
}
constexpr __host__ __device__ double v_of(int l, int m, int mp) {
    int am = m < 0 ? -m : m;
    double d0 = (m == 0) ? 1.0 : 0.0;
    return 0.5 * csqrt_((1.0 + d0) * double((l + am - 1) * (l + am)) / denom_(l, mp))
           * (1.0 - 2.0 * d0);
}
constexpr __host__ __device__ double w_of(int l, int m, int mp) {
    int am = m < 0 ? -m : m;
    double d0 = (m == 0) ? 1.0 : 0.0;
    int wn = l - am - 1; if (wn < 0) wn = 0;
    return -0.5 * csqrt_(double(wn * (l - am)) / denom_(l, mp)) * (1.0 - d0);
}

// ---------------- integer sequence (self-contained) ----------------
template <int... Is> struct ISeq {};
template <int N, int... Is> struct MkSeq : MkSeq<N - 1, N - 1, Is...> {};
template <int... Is> struct MkSeq<0, Is...> { using type = ISeq<Is...>; };

// ---------------- P term (all indices compile-time) ----------------
template <int L, int I, int A, int B>
__device__ __forceinline__ float Pt(const float (&r1)[9],
                                    const float (&dp)[(2 * L - 1) * (2 * L - 1)]) {
    constexpr int lp = L - 1, np = 2 * L - 1, row = (I + 1) * 3;
    if constexpr (B == L)
        return r1[row + 2] * dp[(A + lp) * np + 2 * lp]
             - r1[row + 0] * dp[(A + lp) * np + 0];
    else if constexpr (B == -L)
        return r1[row + 2] * dp[(A + lp) * np + 0]
             + r1[row + 0] * dp[(A + lp) * np + 2 * lp];
    else
        return r1[row + 1] * dp[(A + lp) * np + (B + lp)];
}

// ---------------- one D^L entry (coefficients are immediates) ----------------
template <int L, int M, int MP>
__device__ __forceinline__ float entry(const float (&r1)[9],
                                       const float (&dp)[(2 * L - 1) * (2 * L - 1)]) {
    constexpr float u = (float)u_of(L, M, MP);
    constexpr float v = (float)v_of(L, M, MP);
    constexpr float w = (float)w_of(L, M, MP);
    constexpr float SQ2 = 1.41421356237309515f;
    float acc = 0.0f;
    if constexpr (u != 0.0f)
        acc += u * Pt<L, 0, M, MP>(r1, dp);
    if constexpr (v != 0.0f) {
        if constexpr (M == 0) {
            acc += v * (Pt<L, 1, 1, MP>(r1, dp) + Pt<L, -1, -1, MP>(r1, dp));
        } else if constexpr (M > 0) {
            constexpr float s = (M == 1) ? SQ2 : 1.0f;
            acc += (v * s) * Pt<L, 1, M - 1, MP>(r1, dp);
            if constexpr (M != 1)
                acc -= v * Pt<L, -1, -M + 1, MP>(r1, dp);
        } else {
            if constexpr (M != -1)
                acc += v * Pt<L, 1, M + 1, MP>(r1, dp);
            constexpr float s = (M == -1) ? SQ2 : 1.0f;
            acc += (v * s) * Pt<L, -1, -M - 1, MP>(r1, dp);
        }
    }
    if constexpr (w != 0.0f) {
        if constexpr (M > 0)
            acc += w * (Pt<L, 1, M + 1, MP>(r1, dp) + Pt<L, -1, -M - 1, MP>(r1, dp));
        else
            acc += w * (Pt<L, 1, M - 1, MP>(r1, dp) - Pt<L, -1, -M + 1, MP>(r1, dp));
    }
    return acc;
}

// ---------------- build D^L into registers / into smem ----------------
template <int L, int... Is>
__device__ __forceinline__ void build_reg_impl(const float (&r1)[9],
                                               const float (&dp)[(2 * L - 1) * (2 * L - 1)],
                                               float (&dl)[(2 * L + 1) * (2 * L + 1)],
                                               ISeq<Is...>) {
    ((dl[Is] = entry<L, Is / (2 * L + 1) - L, Is % (2 * L + 1) - L>(r1, dp)), ...);
}
template <int L>
__device__ __forceinline__ void build_reg(const float (&r1)[9],
                                          const float (&dp)[(2 * L - 1) * (2 * L - 1)],
                                          float (&dl)[(2 * L + 1) * (2 * L + 1)]) {
    build_reg_impl<L>(r1, dp, dl, typename MkSeq<(2 * L + 1) * (2 * L + 1)>::type{});
}

template <int L, int... Is>
__device__ __forceinline__ void build_smem_impl(const float (&r1)[9],
                                                const float (&dp)[(2 * L - 1) * (2 * L - 1)],
                                                float* __restrict__ srow, ISeq<Is...>) {
    ((srow[Is] = entry<L, Is / (2 * L + 1) - L, Is % (2 * L + 1) - L>(r1, dp)), ...);
}
template <int L>
__device__ __forceinline__ void build_smem(const float (&r1)[9],
                                           const float (&dp)[(2 * L - 1) * (2 * L - 1)],
                                           float* __restrict__ srow) {
    build_smem_impl<L>(r1, dp, srow, typename MkSeq<(2 * L + 1) * (2 * L + 1)>::type{});
}

// ---------------- output map: 625 -> compact idx, pad -> -1 (zero) ----------
struct CmapT { short v[640]; };
constexpr __host__ __device__ CmapT make_cmap() {
    CmapT c{};
    for (int j = 0; j < 640; j++) c.v[j] = -1;        // zero marker
    for (int j = 0; j < 625; j++) {
        int r = j / 25, cc = j % 25;
        int l = 0;
        while ((l + 1) * (l + 1) <= r) l++;
        int lo = l * l, hi = (l + 1) * (l + 1);
        if (cc >= lo && cc < hi) {
            int base = l * (2 * l - 1) * (2 * l + 1) / 3;   // 0,1,10,35,84
            c.v[j] = (short)(base + (r - lo) * (2 * l + 1) + (cc - lo));
        }
    }
    return c;
}
__device__ const CmapT G_CMAP = make_cmap();

// ---------------- main kernel: one warp per CTA, 32 points ----------------
__global__ void __launch_bounds__(32, 10)
AlignToZWignerD_kernel(const float* __restrict__ xyz, float* __restrict__ out, int N) {
    __shared__ float sm[32 * ROWSTRIDE];
    const int lane = threadIdx.x;
    const int p = blockIdx.x * 32 + lane;
    float* row = sm + lane * ROWSTRIDE;

    if (p < N) {
        // --- geometry ---
        float x = xyz[3 * p + 0], y = xyz[3 * p + 1], z = xyz[3 * p + 2];
        float nrm = sqrtf(x * x + y * y + z * z);
        float inv = 1.0f / fmaxf(nrm, 1e-14f);
        float vx = x * inv, vy = y * inv, vz = z * inv;
        float ct = fminf(1.0f, fmaxf(-1.0f, vz));
        float st = sqrtf(fmaxf(0.0f, 1.0f - ct * ct));
        float rxy = sqrtf(vx * vx + vy * vy);
        float cp, sp;
        if (rxy > 0.0f) { float ir = 1.0f / rxy; cp = vx * ir; sp = vy * ir; }
        else            { cp = 1.0f; sp = 0.0f; }

        // D^1 in real-SH basis (rows/cols permuted by p=[1,2,0])
        float r1[9] = { cp,      0.0f, -sp,
                        st * sp, ct,    st * cp,
                        ct * sp, -st,   ct * cp };

        row[0] = 1.0f;
        #pragma unroll
        for (int i = 0; i < 9; i++) row[1 + i] = r1[i];

        float d2[25];
        build_reg<2>(r1, r1, d2);
        #pragma unroll
        for (int i = 0; i < 25; i++) row[10 + i] = d2[i];

        float d3[49];
        build_reg<3>(r1, d2, d3);
        #pragma unroll
        for (int i = 0; i < 49; i++) row[35 + i] = d3[i];

        build_smem<4>(r1, d3, row + 84);     // 81 entries straight to smem
    }
    __syncwarp();

    // --- write-out: warp streams all 32 points' 625-float rows (coalesced) ---
    // hoist the 20 map values (depend only on lane) + nonzero mask
    int mi[20];
    unsigned nzmask = 0;
    #pragma unroll
    for (int it = 0; it < 20; it++) {
        int j = it * 32 + lane;
        int m = (j < 625) ? (int)G_CMAP.v[j] : -1;
        mi[it] = (m >= 0) ? m : 0;
        if (m >= 0) nzmask |= (1u << it);
    }

    const int blk0 = blockIdx.x * 32;
    float* o = out + (size_t)blk0 * 625 + lane;
    const int npt = (blk0 + 32 <= N) ? 32 : (N - blk0 > 0 ? N - blk0 : 0);

    #pragma unroll 2
    for (int pt = 0; pt < npt; pt++) {
        const float* r = sm + pt * ROWSTRIDE;
        #pragma unroll
        for (int it = 0; it < 20; it++) {
            int j = it * 32;              // + lane folded into o
            if (j + lane < 625) {
                float v = 0.0f;
                if (nzmask & (1u << it)) v = r[mi[it]];   // predicated LDS
                __stcs(o + j, v);                          // streaming store
            }
        }
        o += 625;
    }
}

// ---------------- launch ----------------
extern "C" void kernel_launch(void* const* d_in, const int* in_sizes, int n_in,
                              void* d_out, int out_size) {
    const float* xyz = (const float*)d_in[0];
    float* out = (float*)d_out;
    int N = in_sizes[0] / 3;
    int grid = (N + 31) / 32;
    AlignToZWignerD_kernel<<<grid, 32>>>(xyz, out, N);
}